// round 4
// baseline (speedup 1.0000x reference)
#include <cuda_runtime.h>
#include <cstdint>

#define N1 16384
#define N2 16384
#define G1 8
#define G2 76
#define CHUNK1 2048          // N1 / G1
#define CHUNK2 216           // ceil(N2 / G2): 76*216 = 16416 >= 16384
#define THREADS 256
#define PP 4                 // packed f32x2 lanes per thread -> 8 pos1 points
#define NBLOCKS (G1 * G2)    // 608 = 4 blocks/SM on 152 SMs

// Running min of squared distance per pos1 point, as uint bits (monotone for >=0 floats).
// Statically initialized to +inf bits; atomicMin re-applications across graph replays
// are idempotent (same candidate set each replay -> same fixed point).
struct MinArr {
    unsigned int v[N1];
    constexpr MinArr() : v() {
        for (int i = 0; i < N1; i++) v[i] = 0x7f800000u;
    }
};
__device__ MinArr g_min;
__device__ unsigned int g_done = 0;

__device__ __forceinline__ unsigned long long dup_f32(float v) {
    unsigned int u = __float_as_uint(v);
    return ((unsigned long long)u << 32) | (unsigned long long)u;
}

__device__ __forceinline__ unsigned long long pack2(float lo, float hi) {
    unsigned long long d;
    asm("mov.b64 %0, {%1, %2};" : "=l"(d) : "r"(__float_as_uint(lo)), "r"(__float_as_uint(hi)));
    return d;
}

__device__ __forceinline__ void unpack2(unsigned long long v, float& lo, float& hi) {
    unsigned int a, b;
    asm("mov.b64 {%0, %1}, %2;" : "=r"(a), "=r"(b) : "l"(v));
    lo = __uint_as_float(a);
    hi = __uint_as_float(b);
}

// One pos2 point vs two packed pos1 points:
//   t = fma2(PY, Y, S); t = fma2(PX, X, t); m{lo,hi} = min(m{lo,hi}, t{lo,hi})
// Single asm block so ptxas can alias the pair halves (no MOVs).
__device__ __forceinline__ void step(float& mlo, float& mhi,
                                     unsigned long long PX, unsigned long long PY,
                                     unsigned long long X, unsigned long long Y,
                                     unsigned long long S) {
    asm("{\n\t"
        ".reg .b64 t;\n\t"
        ".reg .b32 tl, th;\n\t"
        "fma.rn.f32x2 t, %2, %3, %4;\n\t"
        "fma.rn.f32x2 t, %5, %6, t;\n\t"
        "mov.b64 {tl, th}, t;\n\t"
        "min.f32 %0, %0, tl;\n\t"
        "min.f32 %1, %1, th;\n\t"
        "}"
        : "+f"(mlo), "+f"(mhi)
        : "l"(PY), "l"(Y), "l"(S), "l"(PX), "l"(X));
}

__global__ __launch_bounds__(THREADS, 4)
void nn_kernel(const float* __restrict__ pos1, const float* __restrict__ pos2,
               float* __restrict__ out) {
    // Per pos2 point (32B stride, interleaved): {x2|x2, y2|y2, sn|sn, pad}
    // where x2=-2x, y2=-2y, sn=x^2+y^2, each duplicated into both f32x2 lanes.
    __shared__ unsigned long long sh[CHUNK2 * 4];
    __shared__ float red[THREADS];
    __shared__ unsigned int s_last;

    const int tid   = threadIdx.x;
    const int base2 = blockIdx.x * CHUNK2;
    const int base1 = blockIdx.y * CHUNK1;

    if (tid < CHUNK2) {
        int idx = base2 + tid;
        float x2, y2, sn;
        if (idx < N2) {
            float x = pos2[2 * idx + 0];
            float y = pos2[2 * idx + 1];
            x2 = -2.0f * x;
            y2 = -2.0f * y;
            sn = fmaf(x, x, y * y);
        } else {
            // sentinel: t = fma(px,0, fma(py,0, inf)) = +inf, never selected
            x2 = 0.0f; y2 = 0.0f; sn = __uint_as_float(0x7f800000u);
        }
        sh[4 * tid + 0] = dup_f32(x2);
        sh[4 * tid + 1] = dup_f32(y2);
        sh[4 * tid + 2] = dup_f32(sn);
    }

    // 8 pos1 points per thread (coalesced, stride THREADS), packed as lanes (k, k+4).
    unsigned long long PX[PP], PY[PP];
    float m[2 * PP];
    {
        float px[2 * PP], py[2 * PP];
#pragma unroll
        for (int k = 0; k < 2 * PP; k++) {
            int idx = base1 + tid + k * THREADS;
            px[k] = pos1[2 * idx + 0];
            py[k] = pos1[2 * idx + 1];
            m[k] = __uint_as_float(0x7f800000u);
        }
#pragma unroll
        for (int k = 0; k < PP; k++) {
            PX[k] = pack2(px[k], px[k + PP]);
            PY[k] = pack2(py[k], py[k + PP]);
        }
    }
    __syncthreads();

#pragma unroll 4
    for (int j = 0; j < CHUNK2; j++) {
        unsigned long long X = sh[4 * j + 0];
        unsigned long long Y = sh[4 * j + 1];
        unsigned long long S = sh[4 * j + 2];
#pragma unroll
        for (int k = 0; k < PP; k++) {
            step(m[k], m[k + PP], PX[k], PY[k], X, Y, S);
        }
    }

    // Epilogue: d2 = |p|^2 + min_t, clamp >= 0, fold into global min (atomic MIN).
#pragma unroll
    for (int k = 0; k < PP; k++) {
        float xlo, xhi, ylo, yhi;
        unpack2(PX[k], xlo, xhi);
        unpack2(PY[k], ylo, yhi);
        {
            int idx  = base1 + tid + k * THREADS;
            float pn = fmaf(xlo, xlo, ylo * ylo);
            float d2 = fmaxf(pn + m[k], 0.0f);
            atomicMin(&g_min.v[idx], __float_as_uint(d2));
        }
        {
            int idx  = base1 + tid + (k + PP) * THREADS;
            float pn = fmaf(xhi, xhi, yhi * yhi);
            float d2 = fmaxf(pn + m[k + PP], 0.0f);
            atomicMin(&g_min.v[idx], __float_as_uint(d2));
        }
    }

    // Make this block's global atomics visible device-wide, then count blocks in.
    __threadfence();
    __syncthreads();
    if (tid == 0) {
        unsigned int prev = atomicAdd(&g_done, 1u);
        s_last = (prev == (unsigned int)(NBLOCKS - 1)) ? 1u : 0u;
    }
    __syncthreads();

    if (s_last) {
        __threadfence();  // order the counter observation before the global reads
        float s = 0.0f;
        for (int i = tid; i < N1; i += THREADS) {
            s += sqrtf(__uint_as_float(__ldcg(&g_min.v[i])));
        }
        red[tid] = s;
        __syncthreads();
        for (int w = THREADS / 2; w > 0; w >>= 1) {
            if (tid < w) red[tid] += red[tid + w];
            __syncthreads();
        }
        if (tid == 0) {
            out[0] = red[0] * (1.0f / (float)N1);
            g_done = 0;  // reset for next replay
        }
    }
}

extern "C" void kernel_launch(void* const* d_in, const int* in_sizes, int n_in,
                              void* d_out, int out_size) {
    const float* pos1 = (const float*)d_in[0];
    const float* pos2 = (const float*)d_in[1];
    float* out = (float*)d_out;

    dim3 grid(G2, G1);
    nn_kernel<<<grid, THREADS>>>(pos1, pos2, out);
}

// round 5
// speedup vs baseline: 1.1950x; 1.1950x over previous
#include <cuda_runtime.h>
#include <cstdint>

#define N1 16384
#define N2 16384
#define G1 4
#define G2 76
#define CHUNK1 4096          // N1 / G1
#define CHUNK2 216           // ceil(N2 / G2): 76*216 = 16416 >= 16384
#define THREADS 256
#define PP 8                 // packed f32x2 lanes per thread -> 16 pos1 points
#define COLS 80              // G2 padded to 80 for float4-aligned rows
#define RBLOCKS 64           // reduce-1 blocks

// Partial min-d^2 buffer: g_part[pos1][col], col = blockIdx.x. Fully overwritten
// every launch (no init needed, replay-idempotent). 5.2 MB -> L2 resident.
__device__ float g_part[N1][COLS];
__device__ float g_bsum[RBLOCKS];

__device__ __forceinline__ unsigned long long dup_f32(float v) {
    unsigned int u = __float_as_uint(v);
    return ((unsigned long long)u << 32) | (unsigned long long)u;
}

__device__ __forceinline__ unsigned long long pack2(float lo, float hi) {
    unsigned long long d;
    asm("mov.b64 %0, {%1, %2};" : "=l"(d) : "r"(__float_as_uint(lo)), "r"(__float_as_uint(hi)));
    return d;
}

__device__ __forceinline__ void unpack2(unsigned long long v, float& lo, float& hi) {
    unsigned int a, b;
    asm("mov.b64 {%0, %1}, %2;" : "=r"(a), "=r"(b) : "l"(v));
    lo = __uint_as_float(a);
    hi = __uint_as_float(b);
}

// One pos2 point vs two packed pos1 points:
//   t = fma2(PY, Y, S); t = fma2(PX, X, t); m{lo,hi} = min(m{lo,hi}, t{lo,hi})
// Single asm block so ptxas aliases the pair halves (no MOVs materialized).
__device__ __forceinline__ void step(float& mlo, float& mhi,
                                     unsigned long long PX, unsigned long long PY,
                                     unsigned long long X, unsigned long long Y,
                                     unsigned long long S) {
    asm("{\n\t"
        ".reg .b64 t;\n\t"
        ".reg .b32 tl, th;\n\t"
        "fma.rn.f32x2 t, %2, %3, %4;\n\t"
        "fma.rn.f32x2 t, %5, %6, t;\n\t"
        "mov.b64 {tl, th}, t;\n\t"
        "min.f32 %0, %0, tl;\n\t"
        "min.f32 %1, %1, th;\n\t"
        "}"
        : "+f"(mlo), "+f"(mhi)
        : "l"(PY), "l"(Y), "l"(S), "l"(PX), "l"(X));
}

__global__ __launch_bounds__(THREADS, 2)
void nn_kernel(const float* __restrict__ pos1, const float* __restrict__ pos2) {
    // Per pos2 point (32B stride, interleaved): {x2|x2, y2|y2, sn|sn, pad}
    // where x2=-2x, y2=-2y, sn=x^2+y^2, each duplicated into both f32x2 lanes.
    __shared__ unsigned long long sh[CHUNK2 * 4];

    const int tid   = threadIdx.x;
    const int bx    = blockIdx.x;
    const int base2 = bx * CHUNK2;
    const int base1 = blockIdx.y * CHUNK1;

    if (tid < CHUNK2) {
        int idx = base2 + tid;
        float x2, y2, sn;
        if (idx < N2) {
            float x = pos2[2 * idx + 0];
            float y = pos2[2 * idx + 1];
            x2 = -2.0f * x;
            y2 = -2.0f * y;
            sn = fmaf(x, x, y * y);
        } else {
            // sentinel: t = fma(px,0, fma(py,0, inf)) = +inf, never selected
            x2 = 0.0f; y2 = 0.0f; sn = __uint_as_float(0x7f800000u);
        }
        sh[4 * tid + 0] = dup_f32(x2);
        sh[4 * tid + 1] = dup_f32(y2);
        sh[4 * tid + 2] = dup_f32(sn);
    }

    // 16 pos1 points per thread (coalesced, stride THREADS), packed as lanes (k, k+8).
    unsigned long long PX[PP], PY[PP];
    float m[2 * PP];
    {
        float px[2 * PP], py[2 * PP];
#pragma unroll
        for (int k = 0; k < 2 * PP; k++) {
            int idx = base1 + tid + k * THREADS;
            px[k] = pos1[2 * idx + 0];
            py[k] = pos1[2 * idx + 1];
            m[k] = __uint_as_float(0x7f800000u);
        }
#pragma unroll
        for (int k = 0; k < PP; k++) {
            PX[k] = pack2(px[k], px[k + PP]);
            PY[k] = pack2(py[k], py[k + PP]);
        }
    }
    __syncthreads();

#pragma unroll 4
    for (int j = 0; j < CHUNK2; j++) {
        unsigned long long X = sh[4 * j + 0];
        unsigned long long Y = sh[4 * j + 1];
        unsigned long long S = sh[4 * j + 2];
#pragma unroll
        for (int k = 0; k < PP; k++) {
            step(m[k], m[k + PP], PX[k], PY[k], X, Y, S);
        }
    }

    // Epilogue: d2 = |p|^2 + min_t, clamp >= 0, plain store (no atomics).
#pragma unroll
    for (int k = 0; k < PP; k++) {
        float xlo, xhi, ylo, yhi;
        unpack2(PX[k], xlo, xhi);
        unpack2(PY[k], ylo, yhi);
        {
            int idx  = base1 + tid + k * THREADS;
            float pn = fmaf(xlo, xlo, ylo * ylo);
            g_part[idx][bx] = fmaxf(pn + m[k], 0.0f);
        }
        {
            int idx  = base1 + tid + (k + PP) * THREADS;
            float pn = fmaf(xhi, xhi, yhi * yhi);
            g_part[idx][bx] = fmaxf(pn + m[k + PP], 0.0f);
        }
    }
}

// Reduce 1: per pos1 point, min over G2 partials, sqrt, deterministic block sum.
__global__ __launch_bounds__(THREADS, 2)
void reduce1_kernel() {
    __shared__ float red[THREADS];
    const int tid = threadIdx.x;
    const int row = blockIdx.x * THREADS + tid;   // one pos1 point per thread

    const float4* rp = (const float4*)&g_part[row][0];
    float mn = __uint_as_float(0x7f800000u);
#pragma unroll
    for (int q = 0; q < G2 / 4; q++) {            // 76/4 = 19 float4 loads
        float4 v = rp[q];
        mn = fminf(mn, fminf(fminf(v.x, v.y), fminf(v.z, v.w)));
    }
    red[tid] = sqrtf(mn);
    __syncthreads();
    for (int w = THREADS / 2; w > 0; w >>= 1) {
        if (tid < w) red[tid] += red[tid + w];
        __syncthreads();
    }
    if (tid == 0) g_bsum[blockIdx.x] = red[0];
}

// Reduce 2: sum 64 block partials -> mean.
__global__ void reduce2_kernel(float* __restrict__ out) {
    __shared__ float red[RBLOCKS];
    const int tid = threadIdx.x;
    red[tid] = g_bsum[tid];
    __syncthreads();
    for (int w = RBLOCKS / 2; w > 0; w >>= 1) {
        if (tid < w) red[tid] += red[tid + w];
        __syncthreads();
    }
    if (tid == 0) out[0] = red[0] * (1.0f / (float)N1);
}

extern "C" void kernel_launch(void* const* d_in, const int* in_sizes, int n_in,
                              void* d_out, int out_size) {
    const float* pos1 = (const float*)d_in[0];
    const float* pos2 = (const float*)d_in[1];
    float* out = (float*)d_out;

    dim3 grid(G2, G1);
    nn_kernel<<<grid, THREADS>>>(pos1, pos2);
    reduce1_kernel<<<N1 / THREADS, THREADS>>>();
    reduce2_kernel<<<1, RBLOCKS>>>(out);
}